// round 9
// baseline (speedup 1.0000x reference)
#include <cuda_runtime.h>
#include <math.h>

#define EMB   128
#define NSP   95
#define NPAIR (NSP * NSP)
#define NRBF  16
#define EPW   4
#define EMAX  300000

// ---------------- device-global scratch ----------------
__device__ float g_Wc[NRBF * EMB];
__device__ float g_bias[EMB];
__device__ float g_T1[NSP * EMB];
__device__ float g_T2[NSP * EMB];
__device__ float g_U1[NSP * 3 * EMB];
__device__ float g_U2[NSP * 3 * EMB];
__device__ float g_Vs1[NSP * 6 * EMB];     // fp32 symmetrized V, [z][pair][m]
__device__ float g_Vs2[NSP * 6 * EMB];
__device__ float g_C[3 * EMB];
__device__ float g_S1[NSP * 3];
__device__ float g_S2[NSP * 3];
__device__ float g_sb;
// edge binning
__device__ int g_cnt[NPAIR];
__device__ int g_cur[NPAIR];
__device__ int g_off[NPAIR + 1];
__device__ int g_perm[EMAX];

// ---------------- precompute 1: scalar tables + U tables + C + S (merged) ----------------
__global__ void pre_tables(const float* __restrict__ W_rbf,
                           const float* __restrict__ b_rbf,
                           const float* __restrict__ W_scalar,
                           const float* __restrict__ b_scalar,
                           const float* __restrict__ emb,
                           const float* __restrict__ vemb,
                           const float* __restrict__ W_vector,
                           const float* __restrict__ b_vector,
                           const float* __restrict__ W_v2s) {
    __shared__ float sh[128];
    int m = threadIdx.x;
    int b = blockIdx.x;
    if (b < NRBF) {
        float s = 0.f;
        #pragma unroll 4
        for (int c = 0; c < EMB; c++)
            s = fmaf(W_rbf[b * EMB + c], W_scalar[(2 * EMB + c) * EMB + m], s);
        g_Wc[b * EMB + m] = s;
    } else if (b == NRBF) {
        float s = b_scalar[m];
        #pragma unroll 4
        for (int c = 0; c < EMB; c++)
            s = fmaf(b_rbf[c], W_scalar[(2 * EMB + c) * EMB + m], s);
        g_bias[m] = s;
    } else if (b < NRBF + 1 + NSP) {
        int z = b - NRBF - 1;
        float s1 = 0.f, s2 = 0.f;
        #pragma unroll 4
        for (int k = 0; k < EMB; k++) {
            float e = emb[z * EMB + k];
            s1 = fmaf(e, W_scalar[k * EMB + m], s1);
            s2 = fmaf(e, W_scalar[(EMB + k) * EMB + m], s2);
        }
        g_T1[z * EMB + m] = s1;
        g_T2[z * EMB + m] = s2;
    } else if (b < NRBF + 1 + NSP + NSP * 3) {
        int zz = b - (NRBF + 1 + NSP);
        int z = zz / 3, d = zz % 3;
        float u1 = 0.f, u2 = 0.f;
        #pragma unroll 4
        for (int k = 0; k < EMB; k++) {
            float v = vemb[(z * EMB + k) * 3 + d];
            u1 = fmaf(v, W_vector[k * EMB + m], u1);
            u2 = fmaf(v, W_vector[(EMB + k) * EMB + m], u2);
        }
        g_U1[(z * 3 + d) * EMB + m] = u1;
        g_U2[(z * 3 + d) * EMB + m] = u2;
        sh[m] = u1; __syncthreads();
        for (int s = 64; s > 0; s >>= 1) { if (m < s) sh[m] += sh[m + s]; __syncthreads(); }
        if (m == 0) g_S1[z * 3 + d] = sh[0];
        __syncthreads();
        sh[m] = u2; __syncthreads();
        for (int s = 64; s > 0; s >>= 1) { if (m < s) sh[m] += sh[m + s]; __syncthreads(); }
        if (m == 0) g_S2[z * 3 + d] = sh[0];
    } else {
        int dp = b - (NRBF + 1 + NSP + NSP * 3); // 0..2
        float s = 0.f;
        #pragma unroll 4
        for (int k = 0; k < EMB; k++)
            s = fmaf(b_vector[k], W_v2s[(k * 3 + dp) * EMB + m], s);
        g_C[dp * EMB + m] = s;
        if (dp == 0) {
            sh[m] = b_vector[m]; __syncthreads();
            for (int s2 = 64; s2 > 0; s2 >>= 1) { if (m < s2) sh[m] += sh[m + s2]; __syncthreads(); }
            if (m == 0) g_sb = sh[0];
        }
    }
}

// ---------------- precompute 2: symmetrized V (fp32, [z][pair][m]) ----------------
__global__ void pre_V(const float* __restrict__ W_v2s) {
    int m = threadIdx.x;
    int b = blockIdx.x;  // 0..569
    int p = b / NSP, z = b % NSP;
    const int PD[6]  = {0, 1, 2, 0, 0, 1};
    const int PDP[6] = {0, 1, 2, 1, 2, 2};
    int d = PD[p], dp = PDP[p];
    float v1 = 0.f, v2 = 0.f;
    #pragma unroll 4
    for (int k = 0; k < EMB; k++) {
        float w = W_v2s[(k * 3 + dp) * EMB + m];
        v1 = fmaf(g_U1[(z * 3 + d) * EMB + k], w, v1);
        v2 = fmaf(g_U2[(z * 3 + d) * EMB + k], w, v2);
    }
    if (d != dp) {
        #pragma unroll 4
        for (int k = 0; k < EMB; k++) {
            float w = W_v2s[(k * 3 + d) * EMB + m];
            v1 = fmaf(g_U1[(z * 3 + dp) * EMB + k], w, v1);
            v2 = fmaf(g_U2[(z * 3 + dp) * EMB + k], w, v2);
        }
    }
    g_Vs1[(z * 6 + p) * EMB + m] = v1;
    g_Vs2[(z * 6 + p) * EMB + m] = v2;
}

// ---------------- binning kernels ----------------
__global__ void zero_k() {
    int i = blockIdx.x * 256 + threadIdx.x;
    if (i < NPAIR) { g_cnt[i] = 0; g_cur[i] = 0; }
}

__global__ void hist_k(const int* __restrict__ idnb_i, const int* __restrict__ idnb_j,
                       const int* __restrict__ Z, int E) {
    int e = blockIdx.x * 256 + threadIdx.x;
    if (e < E) {
        int pr = Z[idnb_i[e]] * NSP + Z[idnb_j[e]];
        atomicAdd(&g_cnt[pr], 1);
    }
}

__global__ void scan_k() {
    __shared__ int sh[1024];
    int t = threadIdx.x;
    const int IPT = (NPAIR + 1023) / 1024;  // 9
    int loc[IPT];
    int sum = 0;
    #pragma unroll
    for (int i = 0; i < IPT; i++) {
        int idx = t * IPT + i;
        int v = (idx < NPAIR) ? g_cnt[idx] : 0;
        loc[i] = sum; sum += v;
    }
    sh[t] = sum; __syncthreads();
    for (int s = 1; s < 1024; s <<= 1) {
        int v = (t >= s) ? sh[t - s] : 0;
        __syncthreads();
        sh[t] += v;
        __syncthreads();
    }
    int base = (t > 0) ? sh[t - 1] : 0;
    #pragma unroll
    for (int i = 0; i < IPT; i++) {
        int idx = t * IPT + i;
        if (idx < NPAIR) g_off[idx] = base + loc[i];
    }
    if (t == 0) g_off[NPAIR] = sh[1023];
}

__global__ void scatter_k(const int* __restrict__ idnb_i, const int* __restrict__ idnb_j,
                          const int* __restrict__ Z, int E) {
    int e = blockIdx.x * 256 + threadIdx.x;
    if (e < E) {
        int pr = Z[idnb_i[e]] * NSP + Z[idnb_j[e]];
        int pos = g_off[pr] + atomicAdd(&g_cur[pr], 1);
        g_perm[pos] = e;
    }
}

// ---------------- main edge kernel: one block per species pair ----------------
__global__ __launch_bounds__(256, 4)
void edge_kernel(const float* __restrict__ rbf,
                 const int* __restrict__ idnb_i,
                 const int* __restrict__ idnb_j,
                 const float* __restrict__ R,
                 float* __restrict__ out,
                 int E) {
    int pair = blockIdx.x;
    int beg = g_off[pair], end = g_off[pair + 1];
    if (beg == end) return;   // block-uniform

    int zi = pair / NSP, zj = pair % NSP;

    __shared__ float s_Wc[NRBF * EMB];   // 8 KB
    __shared__ float s_C[3 * EMB];       // 1.5 KB
    __shared__ float s_V[6 * EMB];       // 3 KB  (pair-combined, fp32)
    __shared__ float s_Tc[EMB];          // 0.5 KB

    for (int i = threadIdx.x; i < NRBF * EMB; i += 256) s_Wc[i] = g_Wc[i];
    for (int i = threadIdx.x; i < 3 * EMB; i += 256)    s_C[i] = g_C[i];
    for (int i = threadIdx.x; i < 6 * EMB; i += 256) {
        int p = i >> 7, m = i & 127;
        s_V[i] = g_Vs1[(zi * 6 + p) * EMB + m] + g_Vs2[(zj * 6 + p) * EMB + m];
    }
    for (int i = threadIdx.x; i < EMB; i += 256)
        s_Tc[i] = g_T1[zi * EMB + i] + g_T2[zj * EMB + i] + g_bias[i];
    // pair-level S coefficients (broadcast loads, cheap)
    float sc0 = g_S1[zi * 3 + 0] + g_S2[zj * 3 + 0];
    float sc1 = g_S1[zi * 3 + 1] + g_S2[zj * 3 + 1];
    float sc2 = g_S1[zi * 3 + 2] + g_S2[zj * 3 + 2];
    float sb  = g_sb;
    __syncthreads();

    const int lane = threadIdx.x & 31;
    const int wid  = threadIdx.x >> 5;     // 0..7
    const size_t o2 = (size_t)E * EMB;

    const float4* __restrict__ Wcf = reinterpret_cast<const float4*>(s_Wc);
    const float4* __restrict__ Cf  = reinterpret_cast<const float4*>(s_C);
    const float4* __restrict__ Vf  = reinterpret_cast<const float4*>(s_V);
    const float4* __restrict__ Tcf = reinterpret_cast<const float4*>(s_Tc);

    for (int s = beg + wid * EPW; s < end; s += 8 * EPW) {
        float4 acc[EPW];
        float bdx[EPW], bdy[EPW], bdz[EPW];
        int eidx[EPW];
        float rv[EPW];

        // ---- per-edge meta: indices, bond dirs, rbf row, vector output ----
        #pragma unroll
        for (int k = 0; k < EPW; k++) {
            int idx = s + k;
            if (idx >= end) idx = end - 1;      // duplicate tail: same value to same addr, benign
            int edge = g_perm[idx];
            eidx[k] = edge;
            int i = idnb_i[edge];
            int j = idnb_j[edge];
            float bx = R[j * 3 + 0] - R[i * 3 + 0];
            float by = R[j * 3 + 1] - R[i * 3 + 1];
            float bz = R[j * 3 + 2] - R[i * 3 + 2];
            float n = sqrtf(bx * bx + by * by + bz * bz) + 1e-8f;
            float inv = 1.0f / n;
            bdx[k] = bx * inv; bdy[k] = by * inv; bdz[k] = bz * inv;
            rv[k] = rbf[edge * NRBF + (lane & 15)];

            float sx = bdx[k] * sc0 + bdy[k] * sc1 + bdz[k] * sc2 + sb;
            if (lane < 3) {
                float comp = (lane == 0) ? bdx[k] : (lane == 1) ? bdy[k] : bdz[k];
                out[o2 + (size_t)edge * 3 + lane] = comp * sx;
            }
        }

        // ---- acc init: pair table (bias folded in), single LDS row for all edges ----
        {
            float4 tc = Tcf[lane];
            #pragma unroll
            for (int k = 0; k < EPW; k++) acc[k] = tc;
        }

        // ---- rbf @ Wc, Wc row hoisted across edges ----
        #pragma unroll
        for (int r = 0; r < NRBF; r++) {
            float4 w = Wcf[r * 32 + lane];
            #pragma unroll
            for (int k = 0; k < EPW; k++) {
                float c = __shfl_sync(0xffffffffu, rv[k], r);
                acc[k].x = fmaf(c, w.x, acc[k].x);
                acc[k].y = fmaf(c, w.y, acc[k].y);
                acc[k].z = fmaf(c, w.z, acc[k].z);
                acc[k].w = fmaf(c, w.w, acc[k].w);
            }
        }

        // ---- bias-of-vector term ----
        {
            float4 c0 = Cf[lane], c1 = Cf[32 + lane], c2 = Cf[64 + lane];
            #pragma unroll
            for (int k = 0; k < EPW; k++) {
                acc[k].x += bdx[k] * c0.x + bdy[k] * c1.x + bdz[k] * c2.x;
                acc[k].y += bdx[k] * c0.y + bdy[k] * c1.y + bdz[k] * c2.y;
                acc[k].z += bdx[k] * c0.z + bdy[k] * c1.z + bdz[k] * c2.z;
                acc[k].w += bdx[k] * c0.w + bdy[k] * c1.w + bdz[k] * c2.w;
            }
        }

        // ---- quadratic-form pair loop: pair-resident V rows (fp32, LDS hoisted) ----
        const int PD[6]  = {0, 1, 2, 0, 0, 1};
        const int PDP[6] = {0, 1, 2, 1, 2, 2};
        #pragma unroll
        for (int p = 0; p < 6; p++) {
            const int d = PD[p], dp = PDP[p];
            float4 v = Vf[p * 32 + lane];
            #pragma unroll
            for (int k = 0; k < EPW; k++) {
                float b1 = (d  == 0) ? bdx[k] : (d  == 1) ? bdy[k] : bdz[k];
                float b2 = (dp == 0) ? bdx[k] : (dp == 1) ? bdy[k] : bdz[k];
                float c = b1 * b2;
                acc[k].x = fmaf(c, v.x, acc[k].x);
                acc[k].y = fmaf(c, v.y, acc[k].y);
                acc[k].z = fmaf(c, v.z, acc[k].z);
                acc[k].w = fmaf(c, v.w, acc[k].w);
            }
        }

        // ---- store scalar block ----
        #pragma unroll
        for (int k = 0; k < EPW; k++)
            reinterpret_cast<float4*>(out + (size_t)eidx[k] * EMB)[lane] = acc[k];
    }
}

// ---------------- launcher ----------------
extern "C" void kernel_launch(void* const* d_in, const int* in_sizes, int n_in,
                              void* d_out, int out_size) {
    const int*   Z        = (const int*)d_in[0];
    const float* rbf      = (const float*)d_in[1];
    const int*   idnb_i   = (const int*)d_in[2];
    const int*   idnb_j   = (const int*)d_in[3];
    const float* R        = (const float*)d_in[4];
    const float* emb      = (const float*)d_in[5];
    const float* vemb     = (const float*)d_in[6];
    const float* W_rbf    = (const float*)d_in[7];
    const float* b_rbf    = (const float*)d_in[8];
    const float* W_scalar = (const float*)d_in[9];
    const float* b_scalar = (const float*)d_in[10];
    const float* W_vector = (const float*)d_in[11];
    const float* b_vector = (const float*)d_in[12];
    const float* W_v2s    = (const float*)d_in[13];
    int E = in_sizes[2];
    if (E > EMAX) E = EMAX;

    int eb = (E + 255) / 256;
    zero_k<<<(NPAIR + 255) / 256, 256>>>();
    pre_tables<<<NRBF + 1 + NSP + NSP * 3 + 3, 128>>>(W_rbf, b_rbf, W_scalar, b_scalar,
                                                      emb, vemb, W_vector, b_vector, W_v2s);
    hist_k<<<eb, 256>>>(idnb_i, idnb_j, Z, E);
    pre_V<<<6 * NSP, 128>>>(W_v2s);
    scan_k<<<1, 1024>>>();
    scatter_k<<<eb, 256>>>(idnb_i, idnb_j, Z, E);
    edge_kernel<<<NPAIR, 256>>>(rbf, idnb_i, idnb_j, R, (float*)d_out, E);
}